// round 15
// baseline (speedup 1.0000x reference)
#include <cuda_runtime.h>
#include <cuda_bf16.h>
#include <stdint.h>

// Problem constants
#define NPIX  4096
#define CCH   256
#define DQK   32
#define BATCH 8
#define BQ    128
#define BK    128
#define NKT   (NPIX/BK)   // 32

// Scratch (static device arrays: allocation-guard safe)
__device__ __align__(256) __nv_bfloat16 g_qh[BATCH * NPIX * DQK];  // [b][n][32] bf16
__device__ __align__(256) __nv_bfloat16 g_kh[BATCH * NPIX * DQK];  // [b][n][32] bf16
__device__ __align__(256) __nv_bfloat16 g_vh[BATCH * CCH * NPIX];  // [b][c][n] bf16

// ---------------------------------------------------------------------------
// PTX helpers
// ---------------------------------------------------------------------------
__device__ __forceinline__ uint32_t smem_u32(const void* p) {
    uint32_t a;
    asm("{ .reg .u64 t; cvta.to.shared.u64 t, %1; cvt.u32.u64 %0, t; }" : "=r"(a) : "l"(p));
    return a;
}
__device__ __forceinline__ void cp_async16(uint32_t dst, const void* src) {
    asm volatile("cp.async.cg.shared.global [%0], [%1], 16;\n" :: "r"(dst), "l"(src));
}
__device__ __forceinline__ void cp_commit() { asm volatile("cp.async.commit_group;\n" ::: "memory"); }
__device__ __forceinline__ void cp_wait0()  { asm volatile("cp.async.wait_group 0;\n" ::: "memory"); }

__device__ __forceinline__ void ldsm_x4(uint32_t& r0, uint32_t& r1, uint32_t& r2, uint32_t& r3,
                                        uint32_t addr) {
    asm volatile("ldmatrix.sync.aligned.m8n8.x4.shared.b16 {%0,%1,%2,%3}, [%4];\n"
                 : "=r"(r0), "=r"(r1), "=r"(r2), "=r"(r3) : "r"(addr));
}
__device__ __forceinline__ void mma_bf16(float* d, const uint32_t* a, uint32_t b0, uint32_t b1) {
    asm volatile(
        "mma.sync.aligned.m16n8k16.row.col.f32.bf16.bf16.f32 "
        "{%0,%1,%2,%3}, {%4,%5,%6,%7}, {%8,%9}, {%0,%1,%2,%3};\n"
        : "+f"(d[0]), "+f"(d[1]), "+f"(d[2]), "+f"(d[3])
        : "r"(a[0]), "r"(a[1]), "r"(a[2]), "r"(a[3]), "r"(b0), "r"(b1));
}
__device__ __forceinline__ uint32_t pack_bf16(float lo, float hi) {
    uint32_t d;
    asm("cvt.rn.bf16x2.f32 %0, %1, %2;" : "=r"(d) : "f"(hi), "f"(lo));  // word = {hi,lo}
    return d;
}

// ---------------------------------------------------------------------------
// Kernel 1: bf16 QKV projection, software-pipelined producer.
// ---------------------------------------------------------------------------
__global__ __launch_bounds__(256, 2) void proj_kernel(
    const float* __restrict__ x,
    const float* __restrict__ Wq, const float* __restrict__ bq,
    const float* __restrict__ Wk, const float* __restrict__ bk,
    const float* __restrict__ Wv, const float* __restrict__ bv)
{
    __shared__ uint32_t Wp[64 * 36];    //  9216 B
    __shared__ uint32_t Xp[32 * 132];   // 16896 B

    const int b   = blockIdx.z;
    const int r0  = blockIdx.y * 64;
    const int n0  = blockIdx.x * 128;
    const int tid = threadIdx.x;
    const int w   = tid >> 5;
    const int lane = tid & 31;
    const int g    = lane >> 2;
    const int tig  = lane & 3;
    const int wr = w >> 2, wn = w & 3;

    const float* xb = x + (size_t)b * CCH * NPIX;

    float4 wreg[4], xra[4], xrb[4];
    auto load_regs = [&](int kc) {
        const int c0 = kc * 64;
#pragma unroll
        for (int i = 0; i < 4; i++) {
            int idx = tid + i * 256;
            int rr = idx >> 4, cs = idx & 15;
            int r = r0 + rr;
            const float* src;
            if (r < 32)       src = Wq + (size_t)r * CCH;
            else if (r < 64)  src = Wk + (size_t)(r - 32) * CCH;
            else              src = Wv + (size_t)(r - 64) * CCH;
            wreg[i] = *(const float4*)(src + c0 + cs * 4);
        }
#pragma unroll
        for (int i = 0; i < 4; i++) {
            int idx = tid + i * 256;
            int c2 = idx >> 5, n4 = idx & 31;
            xra[i] = *(const float4*)(xb + (size_t)(c0 + 2 * c2)     * NPIX + n0 + n4 * 4);
            xrb[i] = *(const float4*)(xb + (size_t)(c0 + 2 * c2 + 1) * NPIX + n0 + n4 * 4);
        }
    };

    load_regs(0);

    float acc[2][4][4];
#pragma unroll
    for (int mf = 0; mf < 2; mf++)
#pragma unroll
        for (int nf = 0; nf < 4; nf++)
#pragma unroll
            for (int i = 0; i < 4; i++) acc[mf][nf][i] = 0.f;

    for (int kc = 0; kc < 4; kc++) {
        __syncthreads();   // previous kc's mma done reading smem

        // pack + STS (regs are dead after this)
#pragma unroll
        for (int i = 0; i < 4; i++) {
            int idx = tid + i * 256;
            int rr = idx >> 4, cs = idx & 15;
            Wp[rr * 36 + cs * 2]     = pack_bf16(wreg[i].x, wreg[i].y);
            Wp[rr * 36 + cs * 2 + 1] = pack_bf16(wreg[i].z, wreg[i].w);
        }
#pragma unroll
        for (int i = 0; i < 4; i++) {
            int idx = tid + i * 256;
            int c2 = idx >> 5, n4 = idx & 31;
            uint32_t* dst = &Xp[c2 * 132 + n4 * 4];
            dst[0] = pack_bf16(xra[i].x, xrb[i].x);
            dst[1] = pack_bf16(xra[i].y, xrb[i].y);
            dst[2] = pack_bf16(xra[i].z, xrb[i].z);
            dst[3] = pack_bf16(xra[i].w, xrb[i].w);
        }
        __syncthreads();

        if (kc + 1 < 4) load_regs(kc + 1);   // LDG latency hides under mma below

        // mma: 4 kd x (2 mf x 4 nf) bf16 m16n8k16
#pragma unroll
        for (int kd = 0; kd < 4; kd++) {
            uint32_t a[2][4];
#pragma unroll
            for (int mf = 0; mf < 2; mf++) {
                int rb = wr * 32 + mf * 16;
                a[mf][0] = Wp[(rb + g)     * 36 + kd * 8 + tig];
                a[mf][1] = Wp[(rb + g + 8) * 36 + kd * 8 + tig];
                a[mf][2] = Wp[(rb + g)     * 36 + kd * 8 + tig + 4];
                a[mf][3] = Wp[(rb + g + 8) * 36 + kd * 8 + tig + 4];
            }
#pragma unroll
            for (int nf = 0; nf < 4; nf++) {
                int nb = wn * 32 + nf * 8 + g;
                uint32_t b0 = Xp[(kd * 8 + tig)     * 132 + nb];
                uint32_t b1 = Xp[(kd * 8 + tig + 4) * 132 + nb];
                mma_bf16(acc[0][nf], a[0], b0, b1);
                mma_bf16(acc[1][nf], a[1], b0, b1);
            }
        }
    }

    // bias + scatter
#pragma unroll
    for (int mf = 0; mf < 2; mf++) {
#pragma unroll
        for (int half = 0; half < 2; half++) {
            const int r = r0 + wr * 32 + mf * 16 + g + half * 8;
            const float* src_b = (r < 32) ? (bq + r) : (r < 64) ? (bk + r - 32) : (bv + r - 64);
            float bias = *src_b;
#pragma unroll
            for (int nf = 0; nf < 4; nf++) {
                const int n = n0 + wn * 32 + nf * 8 + 2 * tig;
                float v0 = acc[mf][nf][half * 2]     + bias;
                float v1 = acc[mf][nf][half * 2 + 1] + bias;
                if (r < 32) {
                    __nv_bfloat16* dq = g_qh + ((size_t)b * NPIX + n) * DQK + r;
                    dq[0]   = __float2bfloat16(v0);
                    dq[DQK] = __float2bfloat16(v1);
                } else if (r < 64) {
                    __nv_bfloat16* dk = g_kh + ((size_t)b * NPIX + n) * DQK + (r - 32);
                    dk[0]   = __float2bfloat16(v0);
                    dk[DQK] = __float2bfloat16(v1);
                } else {
                    uint32_t* dst = (uint32_t*)(g_vh + (size_t)(b * CCH + (r - 64)) * NPIX + n);
                    *dst = pack_bf16(v0, v1);
                }
            }
        }
    }
}

// ---------------------------------------------------------------------------
// Kernel 2: bf16 flash attention, FAT C-WARPS. 256 thr (8 warps), 1 CTA/SM.
//   A-role: warp w owns q rows w*16..+15, full 128 m. exp -> Pb (bf16).
//   C-role: warp (qc2=w>>2 -> 64q, cg=w&3 -> 64c): acc 64q x 64c = 128 regs.
//           V frags shared by 2 warps (was 4) -> stage-C wavefronts halved.
// SMEM identical to round 14: Q[128][80] K x2[128][80] V x2[256][272]
//   Pb[128][272] Ls  = 205824 B
// ---------------------------------------------------------------------------
#define QS_OFF 0
#define KB_OFF 10240
#define KB_BUF 10240
#define VB_OFF 30720
#define VB_BUF 69632
#define PB_OFF 169984
#define LS_OFF 204800
#define ATT_SMEM 205824

__global__ __launch_bounds__(256, 1) void attn_kernel(
    const float* __restrict__ x,
    const float* __restrict__ gamma,
    float* __restrict__ out)
{
    extern __shared__ char smc[];
    const uint32_t smb = smem_u32(smc);

    const int tid  = threadIdx.x;
    const int w    = tid >> 5;
    const int lane = tid & 31;
    const int g    = lane >> 2;
    const int tig  = lane & 3;
    const int b    = blockIdx.y;
    const int n0   = blockIdx.x * BQ;

    const char* qbc = (const char*)(g_qh + (size_t)b * NPIX * DQK);
    const char* kbc = (const char*)(g_kh + (size_t)b * NPIX * DQK);
    const char* vbc = (const char*)(g_vh + (size_t)b * CCH * NPIX);

    // ---- prologue: Q + K(0) + V(0) ----
    {
#pragma unroll
        for (int i = 0; i < 2; i++) {          // Q: 512 chunks
            int idx = tid + i * 256;
            int row = idx >> 2, u = idx & 3;
            cp_async16(smb + QS_OFF + row * 80 + u * 16,
                       qbc + (size_t)(n0 + row) * 64 + u * 16);
        }
#pragma unroll
        for (int i = 0; i < 2; i++) {          // K0: 512 chunks
            int idx = tid + i * 256;
            int row = idx >> 2, u = idx & 3;
            cp_async16(smb + KB_OFF + row * 80 + u * 16, kbc + (size_t)row * 64 + u * 16);
        }
#pragma unroll
        for (int i = 0; i < 16; i++) {         // V0: 4096 chunks
            int idx = tid + i * 256;
            int row = idx >> 4, u = idx & 15;
            cp_async16(smb + VB_OFF + row * 272 + u * 16,
                       vbc + (size_t)row * (2 * NPIX) + u * 16);
        }
        cp_commit();
        cp_wait0();
        __syncthreads();
    }

    // ---- A-role: warp owns rows w*16..+15; preload Q fragments ----
    uint32_t qf0[4], qf1[4];
    {
        const uint32_t qAddr = smb + QS_OFF + (uint32_t)(w * 16 + (lane & 15)) * 80
                             + ((uint32_t)(lane >> 4) << 4);
        ldsm_x4(qf0[0], qf0[1], qf0[2], qf0[3], qAddr);        // k 0-15
        ldsm_x4(qf1[0], qf1[1], qf1[2], qf1[3], qAddr + 32);   // k 16-31
    }

    // ---- C-role ----
    const int qc2 = w >> 2, cg = w & 3;
    const uint32_t aRowOff = (uint32_t)(qc2 * 64 + (lane & 15)) * 272 + ((uint32_t)(lane >> 4) << 4);
    const uint32_t vRowOff = (uint32_t)(cg * 64 + (lane & 15)) * 272 + ((uint32_t)(lane >> 4) << 4);

    float acc[4][8][4];
#pragma unroll
    for (int at = 0; at < 4; at++)
#pragma unroll
        for (int nt = 0; nt < 8; nt++)
#pragma unroll
            for (int i = 0; i < 4; i++) acc[at][nt][i] = 0.f;

    float lp0 = 0.f, lp1 = 0.f;
    const int ar0 = w * 16 + g, ar1 = ar0 + 8;

    for (int kt = 0; kt < NKT; kt++) {
        if (kt) { cp_wait0(); __syncthreads(); }

        // ---- issue L(kt+1) ----
        if (kt + 1 < NKT) {
            const int m0 = (kt + 1) * BK;
            const uint32_t kbuf = smb + KB_OFF + KB_BUF * ((kt + 1) & 1);
            const uint32_t vbuf = smb + VB_OFF + VB_BUF * ((kt + 1) & 1);
#pragma unroll
            for (int i = 0; i < 2; i++) {
                int idx = tid + i * 256;
                int row = idx >> 2, u = idx & 3;
                cp_async16(kbuf + row * 80 + u * 16,
                           kbc + (size_t)(m0 + row) * 64 + u * 16);
            }
#pragma unroll
            for (int i = 0; i < 16; i++) {
                int idx = tid + i * 256;
                int row = idx >> 4, u = idx & 15;
                cp_async16(vbuf + row * 272 + u * 16,
                           vbc + (size_t)row * (2 * NPIX) + 2 * m0 + u * 16);
            }
        }
        cp_commit();

        // ===== A(kt): S[16q x 128m] = Q K^T (bf16) -> exp -> Pb (bf16) =====
        {
            const uint32_t ksB = smb + KB_OFF + KB_BUF * (kt & 1);
            uint32_t* pbW = (uint32_t*)(smc + PB_OFF);
#pragma unroll
            for (int part = 0; part < 4; part++) {     // 32 m-keys per part
                float sv[4][4];
#pragma unroll
                for (int t = 0; t < 4; t++)
#pragma unroll
                    for (int i = 0; i < 4; i++) sv[t][i] = 0.f;
#pragma unroll
                for (int kk = 0; kk < 2; kk++) {
                    const uint32_t* qfk = kk ? qf1 : qf0;
#pragma unroll
                    for (int t2 = 0; t2 < 2; t2++) {
                        uint32_t b0, b1, b2, b3;
                        ldsm_x4(b0, b1, b2, b3,
                                ksB + (uint32_t)(part * 32 + t2 * 16 + (lane & 15)) * 80
                                    + ((uint32_t)(lane >> 4) << 4) + kk * 32);
                        mma_bf16(sv[2 * t2],     qfk, b0, b2);
                        mma_bf16(sv[2 * t2 + 1], qfk, b1, b3);
                    }
                }
#pragma unroll
                for (int t = 0; t < 4; t++) {
                    float p0 = __expf(sv[t][0]);
                    float p1 = __expf(sv[t][1]);
                    float p2 = __expf(sv[t][2]);
                    float p3 = __expf(sv[t][3]);
                    lp0 += p0 + p1;
                    lp1 += p2 + p3;
                    pbW[ar0 * 68 + part * 16 + t * 4 + tig] = pack_bf16(p0, p1);
                    pbW[ar1 * 68 + part * 16 + t * 4 + tig] = pack_bf16(p2, p3);
                }
            }
        }
        __syncthreads();   // Pb(kt) visible

        // ===== C(kt): O[64q x 64c] += P V^T (bf16), 128 m-keys =====
        {
            const uint32_t aBase = smb + PB_OFF + aRowOff;
            const uint32_t vBase = smb + VB_OFF + VB_BUF * (kt & 1) + vRowOff;
#pragma unroll
            for (int kk = 0; kk < 8; kk++) {
                uint32_t A[4][4];
#pragma unroll
                for (int at = 0; at < 4; at++)
                    ldsm_x4(A[at][0], A[at][1], A[at][2], A[at][3],
                            aBase + (uint32_t)at * (16 * 272) + kk * 32);
#pragma unroll
                for (int np = 0; np < 4; np++) {
                    uint32_t v0, v1, v2, v3;
                    ldsm_x4(v0, v1, v2, v3, vBase + (uint32_t)np * (16 * 272) + kk * 32);
#pragma unroll
                    for (int at = 0; at < 4; at++) {
                        mma_bf16(acc[at][2 * np],     A[at], v0, v2);
                        mma_bf16(acc[at][2 * np + 1], A[at], v1, v3);
                    }
                }
            }
        }
    }

    // ---- lsum: quad-reduce, publish (each warp owns its 16 rows fully) ----
    lp0 += __shfl_xor_sync(0xffffffffu, lp0, 1);
    lp0 += __shfl_xor_sync(0xffffffffu, lp0, 2);
    lp1 += __shfl_xor_sync(0xffffffffu, lp1, 1);
    lp1 += __shfl_xor_sync(0xffffffffu, lp1, 2);
    float* Ls = (float*)(smc + LS_OFF);
    if (tig == 0) { Ls[ar0] = lp0; Ls[ar1] = lp1; }
    __syncthreads();

    // ---- epilogue: out = gamma * O / l + x ----
    const float gm = gamma[0];
    const float* xb = x + (size_t)b * CCH * NPIX;
    float* ob = out + (size_t)b * CCH * NPIX;
#pragma unroll
    for (int at = 0; at < 4; at++) {
        const int r0 = qc2 * 64 + at * 16 + g;
        const float sc0 = gm / Ls[r0];
        const float sc1 = gm / Ls[r0 + 8];
#pragma unroll
        for (int nt = 0; nt < 8; nt++) {
            const int c = cg * 64 + nt * 8 + 2 * tig;
            size_t o00 = (size_t)c * NPIX + n0 + r0;
            size_t o01 = o00 + NPIX;
            ob[o00]     = acc[at][nt][0] * sc0 + xb[o00];
            ob[o01]     = acc[at][nt][1] * sc0 + xb[o01];
            ob[o00 + 8] = acc[at][nt][2] * sc1 + xb[o00 + 8];
            ob[o01 + 8] = acc[at][nt][3] * sc1 + xb[o01 + 8];
        }
    }
}

// ---------------------------------------------------------------------------
// Launch
// ---------------------------------------------------------------------------
extern "C" void kernel_launch(void* const* d_in, const int* in_sizes, int n_in,
                              void* d_out, int out_size)
{
    (void)in_sizes; (void)n_in; (void)out_size;
    const float* x     = (const float*)d_in[0];
    const float* Wq    = (const float*)d_in[1];
    const float* bq    = (const float*)d_in[2];
    const float* Wk    = (const float*)d_in[3];
    const float* bk    = (const float*)d_in[4];
    const float* Wv    = (const float*)d_in[5];
    const float* bv    = (const float*)d_in[6];
    const float* gamma = (const float*)d_in[7];
    float* out = (float*)d_out;

    dim3 pgrid(NPIX / 128, 320 / 64, BATCH);
    proj_kernel<<<pgrid, 256>>>(x, Wq, bq, Wk, bk, Wv, bv);

    cudaFuncSetAttribute(attn_kernel, cudaFuncAttributeMaxDynamicSharedMemorySize, ATT_SMEM);
    dim3 agrid(NPIX / BQ, BATCH);
    attn_kernel<<<agrid, 256, ATT_SMEM>>>(x, gamma, out);
}

// round 16
// speedup vs baseline: 1.0409x; 1.0409x over previous
#include <cuda_runtime.h>
#include <cuda_bf16.h>
#include <stdint.h>

// Problem constants
#define NPIX  4096
#define CCH   256
#define DQK   32
#define BATCH 8
#define BQ    128
#define BK    128
#define NKT   (NPIX/BK)   // 32

// Scratch (static device arrays: allocation-guard safe)
__device__ __align__(256) __nv_bfloat16 g_qh[BATCH * NPIX * DQK];  // [b][n][32] bf16
__device__ __align__(256) __nv_bfloat16 g_kh[BATCH * NPIX * DQK];  // [b][n][32] bf16
__device__ __align__(256) __nv_bfloat16 g_vh[BATCH * CCH * NPIX];  // [b][c][n] bf16

// ---------------------------------------------------------------------------
// PTX helpers
// ---------------------------------------------------------------------------
__device__ __forceinline__ uint32_t smem_u32(const void* p) {
    uint32_t a;
    asm("{ .reg .u64 t; cvta.to.shared.u64 t, %1; cvt.u32.u64 %0, t; }" : "=r"(a) : "l"(p));
    return a;
}
__device__ __forceinline__ void cp_async16(uint32_t dst, const void* src) {
    asm volatile("cp.async.cg.shared.global [%0], [%1], 16;\n" :: "r"(dst), "l"(src));
}
__device__ __forceinline__ void cp_commit() { asm volatile("cp.async.commit_group;\n" ::: "memory"); }
__device__ __forceinline__ void cp_wait0()  { asm volatile("cp.async.wait_group 0;\n" ::: "memory"); }

__device__ __forceinline__ void ldsm_x4(uint32_t& r0, uint32_t& r1, uint32_t& r2, uint32_t& r3,
                                        uint32_t addr) {
    asm volatile("ldmatrix.sync.aligned.m8n8.x4.shared.b16 {%0,%1,%2,%3}, [%4];\n"
                 : "=r"(r0), "=r"(r1), "=r"(r2), "=r"(r3) : "r"(addr));
}
__device__ __forceinline__ void mma_bf16(float* d, const uint32_t* a, uint32_t b0, uint32_t b1) {
    asm volatile(
        "mma.sync.aligned.m16n8k16.row.col.f32.bf16.bf16.f32 "
        "{%0,%1,%2,%3}, {%4,%5,%6,%7}, {%8,%9}, {%0,%1,%2,%3};\n"
        : "+f"(d[0]), "+f"(d[1]), "+f"(d[2]), "+f"(d[3])
        : "r"(a[0]), "r"(a[1]), "r"(a[2]), "r"(a[3]), "r"(b0), "r"(b1));
}
__device__ __forceinline__ uint32_t pack_bf16(float lo, float hi) {
    uint32_t d;
    asm("cvt.rn.bf16x2.f32 %0, %1, %2;" : "=r"(d) : "f"(hi), "f"(lo));  // word = {hi,lo}
    return d;
}

// ---------------------------------------------------------------------------
// Kernel 1: bf16 QKV projection, software-pipelined producer (round 15).
// ---------------------------------------------------------------------------
__global__ __launch_bounds__(256, 2) void proj_kernel(
    const float* __restrict__ x,
    const float* __restrict__ Wq, const float* __restrict__ bq,
    const float* __restrict__ Wk, const float* __restrict__ bk,
    const float* __restrict__ Wv, const float* __restrict__ bv)
{
    __shared__ uint32_t Wp[64 * 36];    //  9216 B
    __shared__ uint32_t Xp[32 * 132];   // 16896 B

    const int b   = blockIdx.z;
    const int r0  = blockIdx.y * 64;
    const int n0  = blockIdx.x * 128;
    const int tid = threadIdx.x;
    const int w   = tid >> 5;
    const int lane = tid & 31;
    const int g    = lane >> 2;
    const int tig  = lane & 3;
    const int wr = w >> 2, wn = w & 3;

    const float* xb = x + (size_t)b * CCH * NPIX;

    float4 wreg[4], xra[4], xrb[4];
    auto load_regs = [&](int kc) {
        const int c0 = kc * 64;
#pragma unroll
        for (int i = 0; i < 4; i++) {
            int idx = tid + i * 256;
            int rr = idx >> 4, cs = idx & 15;
            int r = r0 + rr;
            const float* src;
            if (r < 32)       src = Wq + (size_t)r * CCH;
            else if (r < 64)  src = Wk + (size_t)(r - 32) * CCH;
            else              src = Wv + (size_t)(r - 64) * CCH;
            wreg[i] = *(const float4*)(src + c0 + cs * 4);
        }
#pragma unroll
        for (int i = 0; i < 4; i++) {
            int idx = tid + i * 256;
            int c2 = idx >> 5, n4 = idx & 31;
            xra[i] = *(const float4*)(xb + (size_t)(c0 + 2 * c2)     * NPIX + n0 + n4 * 4);
            xrb[i] = *(const float4*)(xb + (size_t)(c0 + 2 * c2 + 1) * NPIX + n0 + n4 * 4);
        }
    };

    load_regs(0);

    float acc[2][4][4];
#pragma unroll
    for (int mf = 0; mf < 2; mf++)
#pragma unroll
        for (int nf = 0; nf < 4; nf++)
#pragma unroll
            for (int i = 0; i < 4; i++) acc[mf][nf][i] = 0.f;

    for (int kc = 0; kc < 4; kc++) {
        __syncthreads();   // previous kc's mma done reading smem

        // pack + STS (regs are dead after this)
#pragma unroll
        for (int i = 0; i < 4; i++) {
            int idx = tid + i * 256;
            int rr = idx >> 4, cs = idx & 15;
            Wp[rr * 36 + cs * 2]     = pack_bf16(wreg[i].x, wreg[i].y);
            Wp[rr * 36 + cs * 2 + 1] = pack_bf16(wreg[i].z, wreg[i].w);
        }
#pragma unroll
        for (int i = 0; i < 4; i++) {
            int idx = tid + i * 256;
            int c2 = idx >> 5, n4 = idx & 31;
            uint32_t* dst = &Xp[c2 * 132 + n4 * 4];
            dst[0] = pack_bf16(xra[i].x, xrb[i].x);
            dst[1] = pack_bf16(xra[i].y, xrb[i].y);
            dst[2] = pack_bf16(xra[i].z, xrb[i].z);
            dst[3] = pack_bf16(xra[i].w, xrb[i].w);
        }
        __syncthreads();

        if (kc + 1 < 4) load_regs(kc + 1);   // LDG latency hides under mma below

        // mma: 4 kd x (2 mf x 4 nf) bf16 m16n8k16
#pragma unroll
        for (int kd = 0; kd < 4; kd++) {
            uint32_t a[2][4];
#pragma unroll
            for (int mf = 0; mf < 2; mf++) {
                int rb = wr * 32 + mf * 16;
                a[mf][0] = Wp[(rb + g)     * 36 + kd * 8 + tig];
                a[mf][1] = Wp[(rb + g + 8) * 36 + kd * 8 + tig];
                a[mf][2] = Wp[(rb + g)     * 36 + kd * 8 + tig + 4];
                a[mf][3] = Wp[(rb + g + 8) * 36 + kd * 8 + tig + 4];
            }
#pragma unroll
            for (int nf = 0; nf < 4; nf++) {
                int nb = wn * 32 + nf * 8 + g;
                uint32_t b0 = Xp[(kd * 8 + tig)     * 132 + nb];
                uint32_t b1 = Xp[(kd * 8 + tig + 4) * 132 + nb];
                mma_bf16(acc[0][nf], a[0], b0, b1);
                mma_bf16(acc[1][nf], a[1], b0, b1);
            }
        }
    }

    // bias + scatter
#pragma unroll
    for (int mf = 0; mf < 2; mf++) {
#pragma unroll
        for (int half = 0; half < 2; half++) {
            const int r = r0 + wr * 32 + mf * 16 + g + half * 8;
            const float* src_b = (r < 32) ? (bq + r) : (r < 64) ? (bk + r - 32) : (bv + r - 64);
            float bias = *src_b;
#pragma unroll
            for (int nf = 0; nf < 4; nf++) {
                const int n = n0 + wn * 32 + nf * 8 + 2 * tig;
                float v0 = acc[mf][nf][half * 2]     + bias;
                float v1 = acc[mf][nf][half * 2 + 1] + bias;
                if (r < 32) {
                    __nv_bfloat16* dq = g_qh + ((size_t)b * NPIX + n) * DQK + r;
                    dq[0]   = __float2bfloat16(v0);
                    dq[DQK] = __float2bfloat16(v1);
                } else if (r < 64) {
                    __nv_bfloat16* dk = g_kh + ((size_t)b * NPIX + n) * DQK + (r - 32);
                    dk[0]   = __float2bfloat16(v0);
                    dk[DQK] = __float2bfloat16(v1);
                } else {
                    uint32_t* dst = (uint32_t*)(g_vh + (size_t)(b * CCH + (r - 64)) * NPIX + n);
                    *dst = pack_bf16(v0, v1);
                }
            }
        }
    }
}

// ---------------------------------------------------------------------------
// Kernel 2: bf16 flash attention (EXACT round-14 design — best measured attn).
// BK=128, no-max softmax, 512 thr, 1 CTA/SM, fp32 acc.
// ---------------------------------------------------------------------------
#define QS_OFF 0
#define KB_OFF 10240
#define KB_BUF 10240
#define VB_OFF 30720
#define VB_BUF 69632
#define PB_OFF 169984
#define LS_OFF 204800
#define ATT_SMEM 205824

__global__ __launch_bounds__(512, 1) void attn_kernel(
    const float* __restrict__ x,
    const float* __restrict__ gamma,
    float* __restrict__ out)
{
    extern __shared__ char smc[];
    const uint32_t smb = smem_u32(smc);

    const int tid  = threadIdx.x;
    const int w    = tid >> 5;
    const int lane = tid & 31;
    const int g    = lane >> 2;
    const int tig  = lane & 3;
    const int b    = blockIdx.y;
    const int n0   = blockIdx.x * BQ;

    const char* qbc = (const char*)(g_qh + (size_t)b * NPIX * DQK);
    const char* kbc = (const char*)(g_kh + (size_t)b * NPIX * DQK);
    const char* vbc = (const char*)(g_vh + (size_t)b * CCH * NPIX);

    // ---- prologue: Q + K(0) + V(0) ----
    {
        {
            int row = tid >> 2, u = tid & 3;
            cp_async16(smb + QS_OFF + row * 80 + u * 16,
                       qbc + (size_t)(n0 + row) * 64 + u * 16);
        }
        {
            int row = tid >> 2, u = tid & 3;
            cp_async16(smb + KB_OFF + row * 80 + u * 16, kbc + (size_t)row * 64 + u * 16);
        }
#pragma unroll
        for (int i = 0; i < 8; i++) {
            int idx = tid + i * 512;
            int row = idx >> 4, u = idx & 15;
            cp_async16(smb + VB_OFF + row * 272 + u * 16,
                       vbc + (size_t)row * (2 * NPIX) + u * 16);
        }
        cp_commit();
        cp_wait0();
        __syncthreads();
    }

    // ---- stage A role + Q fragment preload ----
    const int qa = w >> 1, mg = w & 1;
    uint32_t qf0[4], qf1[4];
    {
        const uint32_t qAddr = smb + QS_OFF + (uint32_t)(qa * 16 + (lane & 15)) * 80
                             + ((uint32_t)(lane >> 4) << 4);
        ldsm_x4(qf0[0], qf0[1], qf0[2], qf0[3], qAddr);
        ldsm_x4(qf1[0], qf1[1], qf1[2], qf1[3], qAddr + 32);
    }

    // ---- stage C role ----
    const int qc = w >> 2, cg = w & 3;
    const uint32_t aRowOff = (uint32_t)(qc * 32 + (lane & 15)) * 272 + ((uint32_t)(lane >> 4) << 4);
    const uint32_t vRowOff = (uint32_t)(cg * 64 + (lane & 15)) * 272 + ((uint32_t)(lane >> 4) << 4);

    float acc[2][8][4];
#pragma unroll
    for (int mt = 0; mt < 2; mt++)
#pragma unroll
        for (int nt = 0; nt < 8; nt++)
#pragma unroll
            for (int i = 0; i < 4; i++) acc[mt][nt][i] = 0.f;

    float lp0 = 0.f, lp1 = 0.f;
    const int ar0 = qa * 16 + g, ar1 = ar0 + 8;

    for (int kt = 0; kt < NKT; kt++) {
        if (kt) { cp_wait0(); __syncthreads(); }

        // ---- issue L(kt+1) ----
        if (kt + 1 < NKT) {
            const int m0 = (kt + 1) * BK;
            const uint32_t kbuf = smb + KB_OFF + KB_BUF * ((kt + 1) & 1);
            const uint32_t vbuf = smb + VB_OFF + VB_BUF * ((kt + 1) & 1);
            {
                int row = tid >> 2, u = tid & 3;
                cp_async16(kbuf + row * 80 + u * 16,
                           kbc + (size_t)(m0 + row) * 64 + u * 16);
            }
#pragma unroll
            for (int i = 0; i < 8; i++) {
                int idx = tid + i * 512;
                int row = idx >> 4, u = idx & 15;
                cp_async16(vbuf + row * 272 + u * 16,
                           vbc + (size_t)row * (2 * NPIX) + 2 * m0 + u * 16);
            }
        }
        cp_commit();

        // ===== A(kt): S[16q x 64m] = Q K^T (bf16) -> exp -> Pb (bf16) =====
        {
            const uint32_t ksB = smb + KB_OFF + KB_BUF * (kt & 1);
            uint32_t* pbW = (uint32_t*)(smc + PB_OFF);
#pragma unroll
            for (int h = 0; h < 2; h++) {
                float sv[4][4];
#pragma unroll
                for (int q2 = 0; q2 < 4; q2++)
#pragma unroll
                    for (int i = 0; i < 4; i++) sv[q2][i] = 0.f;
#pragma unroll
                for (int kk = 0; kk < 2; kk++) {
                    const uint32_t* qfk = kk ? qf1 : qf0;
#pragma unroll
                    for (int t = 0; t < 2; t++) {
                        const int ntp = h * 2 + t;
                        uint32_t b0, b1, b2, b3;
                        ldsm_x4(b0, b1, b2, b3,
                                ksB + (uint32_t)(mg * 64 + ntp * 16 + (lane & 15)) * 80
                                    + ((uint32_t)(lane >> 4) << 4) + kk * 32);
                        mma_bf16(sv[2 * t],     qfk, b0, b2);
                        mma_bf16(sv[2 * t + 1], qfk, b1, b3);
                    }
                }
#pragma unroll
                for (int t = 0; t < 2; t++) {
                    const int ntp = h * 2 + t;
                    const int wbase = mg * 32 + ntp * 8 + tig;
                    float p0 = __expf(sv[2 * t][0]);
                    float p1 = __expf(sv[2 * t][1]);
                    float p2 = __expf(sv[2 * t][2]);
                    float p3 = __expf(sv[2 * t][3]);
                    float p4 = __expf(sv[2 * t + 1][0]);
                    float p5 = __expf(sv[2 * t + 1][1]);
                    float p6 = __expf(sv[2 * t + 1][2]);
                    float p7 = __expf(sv[2 * t + 1][3]);
                    lp0 += (p0 + p1) + (p4 + p5);
                    lp1 += (p2 + p3) + (p6 + p7);
                    pbW[ar0 * 68 + wbase]     = pack_bf16(p0, p1);
                    pbW[ar1 * 68 + wbase]     = pack_bf16(p2, p3);
                    pbW[ar0 * 68 + wbase + 4] = pack_bf16(p4, p5);
                    pbW[ar1 * 68 + wbase + 4] = pack_bf16(p6, p7);
                }
            }
        }
        __syncthreads();   // Pb(kt) visible

        // ===== C(kt): O[32q x 64c] += P V^T (bf16), 128 m-keys =====
        {
            const uint32_t aBase = smb + PB_OFF + aRowOff;
            const uint32_t vBase = smb + VB_OFF + VB_BUF * (kt & 1) + vRowOff;
#pragma unroll
            for (int kk = 0; kk < 8; kk++) {
                uint32_t A0[4], A1[4];
                ldsm_x4(A0[0], A0[1], A0[2], A0[3], aBase + kk * 32);
                ldsm_x4(A1[0], A1[1], A1[2], A1[3], aBase + 16 * 272 + kk * 32);
#pragma unroll
                for (int np = 0; np < 4; np++) {
                    uint32_t v0, v1, v2, v3;
                    ldsm_x4(v0, v1, v2, v3, vBase + (uint32_t)np * (16 * 272) + kk * 32);
                    mma_bf16(acc[0][2 * np],     A0, v0, v2);
                    mma_bf16(acc[0][2 * np + 1], A0, v1, v3);
                    mma_bf16(acc[1][2 * np],     A1, v0, v2);
                    mma_bf16(acc[1][2 * np + 1], A1, v1, v3);
                }
            }
        }
    }

    // ---- lsum: quad-reduce, publish both m-halves ----
    lp0 += __shfl_xor_sync(0xffffffffu, lp0, 1);
    lp0 += __shfl_xor_sync(0xffffffffu, lp0, 2);
    lp1 += __shfl_xor_sync(0xffffffffu, lp1, 1);
    lp1 += __shfl_xor_sync(0xffffffffu, lp1, 2);
    float* Ls = (float*)(smc + LS_OFF);
    if (tig == 0) {
        Ls[mg * 128 + ar0] = lp0;
        Ls[mg * 128 + ar1] = lp1;
    }
    __syncthreads();

    // ---- epilogue: out = gamma * O / l + x ----
    const float gm = gamma[0];
    const float* xb = x + (size_t)b * CCH * NPIX;
    float* ob = out + (size_t)b * CCH * NPIX;
#pragma unroll
    for (int mt = 0; mt < 2; mt++) {
        const int r0 = qc * 32 + mt * 16 + g;
        const float sc0 = gm / (Ls[r0] + Ls[128 + r0]);
        const float sc1 = gm / (Ls[r0 + 8] + Ls[128 + r0 + 8]);
#pragma unroll
        for (int nt = 0; nt < 8; nt++) {
            const int c = cg * 64 + nt * 8 + 2 * tig;
            size_t o00 = (size_t)c * NPIX + n0 + r0;
            size_t o01 = o00 + NPIX;
            ob[o00]     = acc[mt][nt][0] * sc0 + xb[o00];
            ob[o01]     = acc[mt][nt][1] * sc0 + xb[o01];
            ob[o00 + 8] = acc[mt][nt][2] * sc1 + xb[o00 + 8];
            ob[o01 + 8] = acc[mt][nt][3] * sc1 + xb[o01 + 8];
        }
    }
}

// ---------------------------------------------------------------------------
// Launch
// ---------------------------------------------------------------------------
extern "C" void kernel_launch(void* const* d_in, const int* in_sizes, int n_in,
                              void* d_out, int out_size)
{
    (void)in_sizes; (void)n_in; (void)out_size;
    const float* x     = (const float*)d_in[0];
    const float* Wq    = (const float*)d_in[1];
    const float* bq    = (const float*)d_in[2];
    const float* Wk    = (const float*)d_in[3];
    const float* bk    = (const float*)d_in[4];
    const float* Wv    = (const float*)d_in[5];
    const float* bv    = (const float*)d_in[6];
    const float* gamma = (const float*)d_in[7];
    float* out = (float*)d_out;

    dim3 pgrid(NPIX / 128, 320 / 64, BATCH);
    proj_kernel<<<pgrid, 256>>>(x, Wq, bq, Wk, bk, Wv, bv);

    cudaFuncSetAttribute(attn_kernel, cudaFuncAttributeMaxDynamicSharedMemorySize, ATT_SMEM);
    dim3 agrid(NPIX / BQ, BATCH);
    attn_kernel<<<agrid, 512, ATT_SMEM>>>(x, gamma, out);
}

// round 17
// speedup vs baseline: 1.0595x; 1.0179x over previous
#include <cuda_runtime.h>
#include <cuda_bf16.h>
#include <stdint.h>

// Problem constants
#define NPIX  4096
#define CCH   256
#define DQK   32
#define BATCH 8
#define BQ    128
#define BK    128
#define NKT   (NPIX/BK)   // 32

#define LOG2E 1.4426950408889634f

// Scratch (static device arrays: allocation-guard safe)
// q is pre-scaled by log2(e) so attention can use raw ex2.
__device__ __align__(256) __nv_bfloat16 g_qh[BATCH * NPIX * DQK];  // [b][n][32] bf16
__device__ __align__(256) __nv_bfloat16 g_kh[BATCH * NPIX * DQK];  // [b][n][32] bf16
__device__ __align__(256) __nv_bfloat16 g_vh[BATCH * CCH * NPIX];  // [b][c][n] bf16

// ---------------------------------------------------------------------------
// PTX helpers
// ---------------------------------------------------------------------------
__device__ __forceinline__ uint32_t smem_u32(const void* p) {
    uint32_t a;
    asm("{ .reg .u64 t; cvta.to.shared.u64 t, %1; cvt.u32.u64 %0, t; }" : "=r"(a) : "l"(p));
    return a;
}
__device__ __forceinline__ void cp_async16(uint32_t dst, const void* src) {
    asm volatile("cp.async.cg.shared.global [%0], [%1], 16;\n" :: "r"(dst), "l"(src));
}
__device__ __forceinline__ void cp_commit() { asm volatile("cp.async.commit_group;\n" ::: "memory"); }
__device__ __forceinline__ void cp_wait0()  { asm volatile("cp.async.wait_group 0;\n" ::: "memory"); }

__device__ __forceinline__ void ldsm_x4(uint32_t& r0, uint32_t& r1, uint32_t& r2, uint32_t& r3,
                                        uint32_t addr) {
    asm volatile("ldmatrix.sync.aligned.m8n8.x4.shared.b16 {%0,%1,%2,%3}, [%4];\n"
                 : "=r"(r0), "=r"(r1), "=r"(r2), "=r"(r3) : "r"(addr));
}
__device__ __forceinline__ void mma_bf16(float* d, const uint32_t* a, uint32_t b0, uint32_t b1) {
    asm volatile(
        "mma.sync.aligned.m16n8k16.row.col.f32.bf16.bf16.f32 "
        "{%0,%1,%2,%3}, {%4,%5,%6,%7}, {%8,%9}, {%0,%1,%2,%3};\n"
        : "+f"(d[0]), "+f"(d[1]), "+f"(d[2]), "+f"(d[3])
        : "r"(a[0]), "r"(a[1]), "r"(a[2]), "r"(a[3]), "r"(b0), "r"(b1));
}
__device__ __forceinline__ uint32_t pack_bf16(float lo, float hi) {
    uint32_t d;
    asm("cvt.rn.bf16x2.f32 %0, %1, %2;" : "=r"(d) : "f"(hi), "f"(lo));  // word = {hi,lo}
    return d;
}
__device__ __forceinline__ float ex2f(float x) {    // raw MUFU.EX2 (scores are base-2)
    float r;
    asm("ex2.approx.f32 %0, %1;" : "=f"(r) : "f"(x));
    return r;
}

// ---------------------------------------------------------------------------
// Kernel 1: bf16 QKV projection, software-pipelined producer.
// q rows are scaled by log2(e) at store time.
// ---------------------------------------------------------------------------
__global__ __launch_bounds__(256, 2) void proj_kernel(
    const float* __restrict__ x,
    const float* __restrict__ Wq, const float* __restrict__ bq,
    const float* __restrict__ Wk, const float* __restrict__ bk,
    const float* __restrict__ Wv, const float* __restrict__ bv)
{
    __shared__ uint32_t Wp[64 * 36];    //  9216 B
    __shared__ uint32_t Xp[32 * 132];   // 16896 B

    const int b   = blockIdx.z;
    const int r0  = blockIdx.y * 64;
    const int n0  = blockIdx.x * 128;
    const int tid = threadIdx.x;
    const int w   = tid >> 5;
    const int lane = tid & 31;
    const int g    = lane >> 2;
    const int tig  = lane & 3;
    const int wr = w >> 2, wn = w & 3;

    const float* xb = x + (size_t)b * CCH * NPIX;

    float4 wreg[4], xra[4], xrb[4];
    auto load_regs = [&](int kc) {
        const int c0 = kc * 64;
#pragma unroll
        for (int i = 0; i < 4; i++) {
            int idx = tid + i * 256;
            int rr = idx >> 4, cs = idx & 15;
            int r = r0 + rr;
            const float* src;
            if (r < 32)       src = Wq + (size_t)r * CCH;
            else if (r < 64)  src = Wk + (size_t)(r - 32) * CCH;
            else              src = Wv + (size_t)(r - 64) * CCH;
            wreg[i] = *(const float4*)(src + c0 + cs * 4);
        }
#pragma unroll
        for (int i = 0; i < 4; i++) {
            int idx = tid + i * 256;
            int c2 = idx >> 5, n4 = idx & 31;
            xra[i] = *(const float4*)(xb + (size_t)(c0 + 2 * c2)     * NPIX + n0 + n4 * 4);
            xrb[i] = *(const float4*)(xb + (size_t)(c0 + 2 * c2 + 1) * NPIX + n0 + n4 * 4);
        }
    };

    load_regs(0);

    float acc[2][4][4];
#pragma unroll
    for (int mf = 0; mf < 2; mf++)
#pragma unroll
        for (int nf = 0; nf < 4; nf++)
#pragma unroll
            for (int i = 0; i < 4; i++) acc[mf][nf][i] = 0.f;

    for (int kc = 0; kc < 4; kc++) {
        __syncthreads();   // previous kc's mma done reading smem

#pragma unroll
        for (int i = 0; i < 4; i++) {
            int idx = tid + i * 256;
            int rr = idx >> 4, cs = idx & 15;
            Wp[rr * 36 + cs * 2]     = pack_bf16(wreg[i].x, wreg[i].y);
            Wp[rr * 36 + cs * 2 + 1] = pack_bf16(wreg[i].z, wreg[i].w);
        }
#pragma unroll
        for (int i = 0; i < 4; i++) {
            int idx = tid + i * 256;
            int c2 = idx >> 5, n4 = idx & 31;
            uint32_t* dst = &Xp[c2 * 132 + n4 * 4];
            dst[0] = pack_bf16(xra[i].x, xrb[i].x);
            dst[1] = pack_bf16(xra[i].y, xrb[i].y);
            dst[2] = pack_bf16(xra[i].z, xrb[i].z);
            dst[3] = pack_bf16(xra[i].w, xrb[i].w);
        }
        __syncthreads();

        if (kc + 1 < 4) load_regs(kc + 1);   // LDG latency hides under mma below

#pragma unroll
        for (int kd = 0; kd < 4; kd++) {
            uint32_t a[2][4];
#pragma unroll
            for (int mf = 0; mf < 2; mf++) {
                int rb = wr * 32 + mf * 16;
                a[mf][0] = Wp[(rb + g)     * 36 + kd * 8 + tig];
                a[mf][1] = Wp[(rb + g + 8) * 36 + kd * 8 + tig];
                a[mf][2] = Wp[(rb + g)     * 36 + kd * 8 + tig + 4];
                a[mf][3] = Wp[(rb + g + 8) * 36 + kd * 8 + tig + 4];
            }
#pragma unroll
            for (int nf = 0; nf < 4; nf++) {
                int nb = wn * 32 + nf * 8 + g;
                uint32_t b0 = Xp[(kd * 8 + tig)     * 132 + nb];
                uint32_t b1 = Xp[(kd * 8 + tig + 4) * 132 + nb];
                mma_bf16(acc[0][nf], a[0], b0, b1);
                mma_bf16(acc[1][nf], a[1], b0, b1);
            }
        }
    }

    // bias + scatter (q scaled by log2e)
#pragma unroll
    for (int mf = 0; mf < 2; mf++) {
#pragma unroll
        for (int half = 0; half < 2; half++) {
            const int r = r0 + wr * 32 + mf * 16 + g + half * 8;
            const float* src_b = (r < 32) ? (bq + r) : (r < 64) ? (bk + r - 32) : (bv + r - 64);
            float bias = *src_b;
#pragma unroll
            for (int nf = 0; nf < 4; nf++) {
                const int n = n0 + wn * 32 + nf * 8 + 2 * tig;
                float v0 = acc[mf][nf][half * 2]     + bias;
                float v1 = acc[mf][nf][half * 2 + 1] + bias;
                if (r < 32) {
                    __nv_bfloat16* dq = g_qh + ((size_t)b * NPIX + n) * DQK + r;
                    dq[0]   = __float2bfloat16(v0 * LOG2E);
                    dq[DQK] = __float2bfloat16(v1 * LOG2E);
                } else if (r < 64) {
                    __nv_bfloat16* dk = g_kh + ((size_t)b * NPIX + n) * DQK + (r - 32);
                    dk[0]   = __float2bfloat16(v0);
                    dk[DQK] = __float2bfloat16(v1);
                } else {
                    uint32_t* dst = (uint32_t*)(g_vh + (size_t)(b * CCH + (r - 64)) * NPIX + n);
                    *dst = pack_bf16(v0, v1);
                }
            }
        }
    }
}

// ---------------------------------------------------------------------------
// Kernel 2: bf16 flash attention (round-14 design; exp -> raw ex2).
// BK=128, no-max softmax (base-2 scores), 512 thr, 1 CTA/SM, fp32 acc.
// ---------------------------------------------------------------------------
#define QS_OFF 0
#define KB_OFF 10240
#define KB_BUF 10240
#define VB_OFF 30720
#define VB_BUF 69632
#define PB_OFF 169984
#define LS_OFF 204800
#define ATT_SMEM 205824

__global__ __launch_bounds__(512, 1) void attn_kernel(
    const float* __restrict__ x,
    const float* __restrict__ gamma,
    float* __restrict__ out)
{
    extern __shared__ char smc[];
    const uint32_t smb = smem_u32(smc);

    const int tid  = threadIdx.x;
    const int w    = tid >> 5;
    const int lane = tid & 31;
    const int g    = lane >> 2;
    const int tig  = lane & 3;
    const int b    = blockIdx.y;
    const int n0   = blockIdx.x * BQ;

    const char* qbc = (const char*)(g_qh + (size_t)b * NPIX * DQK);
    const char* kbc = (const char*)(g_kh + (size_t)b * NPIX * DQK);
    const char* vbc = (const char*)(g_vh + (size_t)b * CCH * NPIX);

    // ---- prologue: Q + K(0) + V(0) ----
    {
        {
            int row = tid >> 2, u = tid & 3;
            cp_async16(smb + QS_OFF + row * 80 + u * 16,
                       qbc + (size_t)(n0 + row) * 64 + u * 16);
        }
        {
            int row = tid >> 2, u = tid & 3;
            cp_async16(smb + KB_OFF + row * 80 + u * 16, kbc + (size_t)row * 64 + u * 16);
        }
#pragma unroll
        for (int i = 0; i < 8; i++) {
            int idx = tid + i * 512;
            int row = idx >> 4, u = idx & 15;
            cp_async16(smb + VB_OFF + row * 272 + u * 16,
                       vbc + (size_t)row * (2 * NPIX) + u * 16);
        }
        cp_commit();
        cp_wait0();
        __syncthreads();
    }

    // ---- stage A role + Q fragment preload ----
    const int qa = w >> 1, mg = w & 1;
    uint32_t qf0[4], qf1[4];
    {
        const uint32_t qAddr = smb + QS_OFF + (uint32_t)(qa * 16 + (lane & 15)) * 80
                             + ((uint32_t)(lane >> 4) << 4);
        ldsm_x4(qf0[0], qf0[1], qf0[2], qf0[3], qAddr);
        ldsm_x4(qf1[0], qf1[1], qf1[2], qf1[3], qAddr + 32);
    }

    // ---- stage C role ----
    const int qc = w >> 2, cg = w & 3;
    const uint32_t aRowOff = (uint32_t)(qc * 32 + (lane & 15)) * 272 + ((uint32_t)(lane >> 4) << 4);
    const uint32_t vRowOff = (uint32_t)(cg * 64 + (lane & 15)) * 272 + ((uint32_t)(lane >> 4) << 4);

    float acc[2][8][4];
#pragma unroll
    for (int mt = 0; mt < 2; mt++)
#pragma unroll
        for (int nt = 0; nt < 8; nt++)
#pragma unroll
            for (int i = 0; i < 4; i++) acc[mt][nt][i] = 0.f;

    float lp0 = 0.f, lp1 = 0.f;
    const int ar0 = qa * 16 + g, ar1 = ar0 + 8;

    for (int kt = 0; kt < NKT; kt++) {
        if (kt) { cp_wait0(); __syncthreads(); }

        // ---- issue L(kt+1) ----
        if (kt + 1 < NKT) {
            const int m0 = (kt + 1) * BK;
            const uint32_t kbuf = smb + KB_OFF + KB_BUF * ((kt + 1) & 1);
            const uint32_t vbuf = smb + VB_OFF + VB_BUF * ((kt + 1) & 1);
            {
                int row = tid >> 2, u = tid & 3;
                cp_async16(kbuf + row * 80 + u * 16,
                           kbc + (size_t)(m0 + row) * 64 + u * 16);
            }
#pragma unroll
            for (int i = 0; i < 8; i++) {
                int idx = tid + i * 512;
                int row = idx >> 4, u = idx & 15;
                cp_async16(vbuf + row * 272 + u * 16,
                           vbc + (size_t)row * (2 * NPIX) + 2 * m0 + u * 16);
            }
        }
        cp_commit();

        // ===== A(kt): S[16q x 64m] (base-2 scores) -> ex2 -> Pb (bf16) =====
        {
            const uint32_t ksB = smb + KB_OFF + KB_BUF * (kt & 1);
            uint32_t* pbW = (uint32_t*)(smc + PB_OFF);
#pragma unroll
            for (int h = 0; h < 2; h++) {
                float sv[4][4];
#pragma unroll
                for (int q2 = 0; q2 < 4; q2++)
#pragma unroll
                    for (int i = 0; i < 4; i++) sv[q2][i] = 0.f;
#pragma unroll
                for (int kk = 0; kk < 2; kk++) {
                    const uint32_t* qfk = kk ? qf1 : qf0;
#pragma unroll
                    for (int t = 0; t < 2; t++) {
                        const int ntp = h * 2 + t;
                        uint32_t b0, b1, b2, b3;
                        ldsm_x4(b0, b1, b2, b3,
                                ksB + (uint32_t)(mg * 64 + ntp * 16 + (lane & 15)) * 80
                                    + ((uint32_t)(lane >> 4) << 4) + kk * 32);
                        mma_bf16(sv[2 * t],     qfk, b0, b2);
                        mma_bf16(sv[2 * t + 1], qfk, b1, b3);
                    }
                }
#pragma unroll
                for (int t = 0; t < 2; t++) {
                    const int ntp = h * 2 + t;
                    const int wbase = mg * 32 + ntp * 8 + tig;
                    float p0 = ex2f(sv[2 * t][0]);
                    float p1 = ex2f(sv[2 * t][1]);
                    float p2 = ex2f(sv[2 * t][2]);
                    float p3 = ex2f(sv[2 * t][3]);
                    float p4 = ex2f(sv[2 * t + 1][0]);
                    float p5 = ex2f(sv[2 * t + 1][1]);
                    float p6 = ex2f(sv[2 * t + 1][2]);
                    float p7 = ex2f(sv[2 * t + 1][3]);
                    lp0 += (p0 + p1) + (p4 + p5);
                    lp1 += (p2 + p3) + (p6 + p7);
                    pbW[ar0 * 68 + wbase]     = pack_bf16(p0, p1);
                    pbW[ar1 * 68 + wbase]     = pack_bf16(p2, p3);
                    pbW[ar0 * 68 + wbase + 4] = pack_bf16(p4, p5);
                    pbW[ar1 * 68 + wbase + 4] = pack_bf16(p6, p7);
                }
            }
        }
        __syncthreads();   // Pb(kt) visible

        // ===== C(kt): O[32q x 64c] += P V^T (bf16), 128 m-keys =====
        {
            const uint32_t aBase = smb + PB_OFF + aRowOff;
            const uint32_t vBase = smb + VB_OFF + VB_BUF * (kt & 1) + vRowOff;
#pragma unroll
            for (int kk = 0; kk < 8; kk++) {
                uint32_t A0[4], A1[4];
                ldsm_x4(A0[0], A0[1], A0[2], A0[3], aBase + kk * 32);
                ldsm_x4(A1[0], A1[1], A1[2], A1[3], aBase + 16 * 272 + kk * 32);
#pragma unroll
                for (int np = 0; np < 4; np++) {
                    uint32_t v0, v1, v2, v3;
                    ldsm_x4(v0, v1, v2, v3, vBase + (uint32_t)np * (16 * 272) + kk * 32);
                    mma_bf16(acc[0][2 * np],     A0, v0, v2);
                    mma_bf16(acc[0][2 * np + 1], A0, v1, v3);
                    mma_bf16(acc[1][2 * np],     A1, v0, v2);
                    mma_bf16(acc[1][2 * np + 1], A1, v1, v3);
                }
            }
        }
    }

    // ---- lsum: quad-reduce, publish both m-halves ----
    lp0 += __shfl_xor_sync(0xffffffffu, lp0, 1);
    lp0 += __shfl_xor_sync(0xffffffffu, lp0, 2);
    lp1 += __shfl_xor_sync(0xffffffffu, lp1, 1);
    lp1 += __shfl_xor_sync(0xffffffffu, lp1, 2);
    float* Ls = (float*)(smc + LS_OFF);
    if (tig == 0) {
        Ls[mg * 128 + ar0] = lp0;
        Ls[mg * 128 + ar1] = lp1;
    }
    __syncthreads();

    // ---- epilogue: out = gamma * O / l + x ----
    const float gm = gamma[0];
    const float* xb = x + (size_t)b * CCH * NPIX;
    float* ob = out + (size_t)b * CCH * NPIX;
#pragma unroll
    for (int mt = 0; mt < 2; mt++) {
        const int r0 = qc * 32 + mt * 16 + g;
        const float sc0 = gm / (Ls[r0] + Ls[128 + r0]);
        const float sc1 = gm / (Ls[r0 + 8] + Ls[128 + r0 + 8]);
#pragma unroll
        for (int nt = 0; nt < 8; nt++) {
            const int c = cg * 64 + nt * 8 + 2 * tig;
            size_t o00 = (size_t)c * NPIX + n0 + r0;
            size_t o01 = o00 + NPIX;
            ob[o00]     = acc[mt][nt][0] * sc0 + xb[o00];
            ob[o01]     = acc[mt][nt][1] * sc0 + xb[o01];
            ob[o00 + 8] = acc[mt][nt][2] * sc1 + xb[o00 + 8];
            ob[o01 + 8] = acc[mt][nt][3] * sc1 + xb[o01 + 8];
        }
    }
}

// ---------------------------------------------------------------------------
// Launch
// ---------------------------------------------------------------------------
extern "C" void kernel_launch(void* const* d_in, const int* in_sizes, int n_in,
                              void* d_out, int out_size)
{
    (void)in_sizes; (void)n_in; (void)out_size;
    const float* x     = (const float*)d_in[0];
    const float* Wq    = (const float*)d_in[1];
    const float* bq    = (const float*)d_in[2];
    const float* Wk    = (const float*)d_in[3];
    const float* bk    = (const float*)d_in[4];
    const float* Wv    = (const float*)d_in[5];
    const float* bv    = (const float*)d_in[6];
    const float* gamma = (const float*)d_in[7];
    float* out = (float*)d_out;

    dim3 pgrid(NPIX / 128, 320 / 64, BATCH);
    proj_kernel<<<pgrid, 256>>>(x, Wq, bq, Wk, bk, Wv, bv);

    cudaFuncSetAttribute(attn_kernel, cudaFuncAttributeMaxDynamicSharedMemorySize, ATT_SMEM);
    dim3 agrid(NPIX / BQ, BATCH);
    attn_kernel<<<agrid, 512, ATT_SMEM>>>(x, gamma, out);
}